// round 5
// baseline (speedup 1.0000x reference)
#include <cuda_runtime.h>
#include <cstdint>

// Problem shape (fixed by reference): B=32, C=256, H=64, W=64
// in:  d_in[0] = data_in   [B,C,H,W] f32  (33,554,432 elems)
//      d_in[1] = td_energy [C]       f32  (256)
//      d_in[2] = td_hist   [100,100] f32  (10,000)
// out: [ data_in copy | energy+meanabs | hist+1 ]  (f32)

static constexpr int B = 32;
static constexpr int C = 256;
static constexpr int HW = 64 * 64;              // 4096 floats per plane
static constexpr int HW4 = HW / 4;              // 1024 float4 per plane
static constexpr long long N_DATA = (long long)B * C * HW;  // 33,554,432
static constexpr float INV_N = 1.0f / (float)(B * HW);      // 1/131072
static constexpr int HIST_N = 10000;
static constexpr int THREADS = 1024;

// One block per channel. Each of the 1024 threads handles exactly one
// float4 per plane, for all 32 planes of this channel. The per-channel
// reduction is entirely block-local: NO global atomics, NO fences, NO
// cross-block state (R3/R4 post-mortem: returning global atomics on the
// block-exit path cost ~3us of block-retirement serialization).
// Blocks 0..9 additionally do the hist (+1) side-task.
__global__ __launch_bounds__(THREADS) void fused_all(
    const float4* __restrict__ in,
    float4* __restrict__ out,
    const float* __restrict__ td_energy,
    const float* __restrict__ td_hist,
    float* __restrict__ out_energy,
    float* __restrict__ out_hist) {

    const int c = blockIdx.x;
    const int tid = threadIdx.x;

    // tiny side-task: hist (+1). 10 blocks x 1024 threads covers 10000.
    if (c < (HIST_N + THREADS - 1) / THREADS) {
        int h = c * THREADS + tid;
        if (h < HIST_N) out_hist[h] = td_hist[h] + 1.0f;
    }

    float s = 0.0f;
#pragma unroll 8
    for (int b = 0; b < B; b++) {
        const size_t off = ((size_t)(b * C + c) << 10) + tid;  // float4 units
        float4 v = in[off];
        out[off] = v;
        s += fabsf(v.x) + fabsf(v.y) + fabsf(v.z) + fabsf(v.w);
    }

    // warp reduce (32 lanes)
#pragma unroll
    for (int o = 16; o > 0; o >>= 1)
        s += __shfl_xor_sync(0xffffffffu, s, o);

    __shared__ float ws[32];
    if ((tid & 31) == 0) ws[tid >> 5] = s;
    __syncthreads();

    if (tid < 32) {
        s = ws[tid];
#pragma unroll
        for (int o = 16; o > 0; o >>= 1)
            s += __shfl_xor_sync(0xffffffffu, s, o);
        if (tid == 0)
            out_energy[c] = td_energy[c] + s * INV_N;  // plain STG, no wait
    }
}

extern "C" void kernel_launch(void* const* d_in, const int* in_sizes, int n_in,
                              void* d_out, int out_size) {
    const float* data_in   = (const float*)d_in[0];
    const float* td_energy = (const float*)d_in[1];
    const float* td_hist   = (const float*)d_in[2];

    float* out        = (float*)d_out;
    float* out_energy = out + N_DATA;
    float* out_hist   = out_energy + C;

    fused_all<<<C, THREADS>>>((const float4*)data_in, (float4*)out,
                              td_energy, td_hist, out_energy, out_hist);
}

// round 6
// speedup vs baseline: 1.0892x; 1.0892x over previous
#include <cuda_runtime.h>
#include <cstdint>

// Problem shape (fixed by reference): B=32, C=256, H=64, W=64
// in:  d_in[0] = data_in   [B,C,H,W] f32  (33,554,432 elems)
//      d_in[1] = td_energy [C]       f32  (256)
//      d_in[2] = td_hist   [100,100] f32  (10,000)
// out: [ data_in copy | energy+meanabs | hist+1 ]  (f32)

static constexpr int B = 32;
static constexpr int C = 256;
static constexpr int HW = 64 * 64;              // 4096 floats per plane
static constexpr int HW4 = HW / 4;              // 1024 float4 per plane
static constexpr long long N_DATA = (long long)B * C * HW;  // 33,554,432
static constexpr float INV_N = 1.0f / (float)(B * HW);      // 1/131072
static constexpr int HIST_N = 10000;

// Node 1: seed out_energy with the base values (bulk kernel atomicAdds
// scaled partials on top). One tiny block.
__global__ void init_energy(const float* __restrict__ td_energy,
                            float* __restrict__ out_energy) {
    out_energy[threadIdx.x] = td_energy[threadIdx.x];
}

// Node 2: bulk copy + reduce. Each block handles TWO planes of the same
// channel (b and b+16), 256 threads x 8 float4. All 8 loads are issued
// front-batched (independent LDG.128 x8 -> deep MLP) before any store.
// Per-block tail: ONE fire-and-forget atomicAdd (no inc/fence chain —
// measured neutral-to-harmful in R2-R5). First 40 blocks also do hist.
__global__ __launch_bounds__(256) void fused_bulk(
    const float4* __restrict__ in,
    float4* __restrict__ out,
    const float* __restrict__ td_hist,
    float* __restrict__ out_energy,
    float* __restrict__ out_hist) {

    const int bid = blockIdx.x;            // 0..4095
    const int c  = bid & (C - 1);          // channel
    const int b0 = bid >> 8;               // 0..15 -> planes b0, b0+16
    const int tid = threadIdx.x;

    // hist side-task: 40 blocks x 256 threads covers 10000
    if (bid < (HIST_N + 255) / 256) {
        int h = bid * 256 + tid;
        if (h < HIST_N) out_hist[h] = td_hist[h] + 1.0f;
    }

    const size_t pA = ((size_t)(b0 * C + c) << 10);          // float4 units
    const size_t pB = ((size_t)((b0 + 16) * C + c) << 10);

    // ---- front-batched loads: 8 independent LDG.128 ----
    float4 v[8];
#pragma unroll
    for (int i = 0; i < 4; i++) v[i]     = in[pA + tid + i * 256];
#pragma unroll
    for (int i = 0; i < 4; i++) v[4 + i] = in[pB + tid + i * 256];

    // ---- stores ----
#pragma unroll
    for (int i = 0; i < 4; i++) out[pA + tid + i * 256] = v[i];
#pragma unroll
    for (int i = 0; i < 4; i++) out[pB + tid + i * 256] = v[4 + i];

    // ---- reduce |x| ----
    float s = 0.0f;
#pragma unroll
    for (int i = 0; i < 8; i++)
        s += fabsf(v[i].x) + fabsf(v[i].y) + fabsf(v[i].z) + fabsf(v[i].w);

#pragma unroll
    for (int o = 16; o > 0; o >>= 1)
        s += __shfl_xor_sync(0xffffffffu, s, o);

    __shared__ float ws[8];
    if ((tid & 31) == 0) ws[tid >> 5] = s;
    __syncthreads();

    if (tid == 0) {
        s = ws[0];
#pragma unroll
        for (int w = 1; w < 8; w++) s += ws[w];
        atomicAdd(&out_energy[c], s * INV_N);   // fire-and-forget
    }
}

extern "C" void kernel_launch(void* const* d_in, const int* in_sizes, int n_in,
                              void* d_out, int out_size) {
    const float* data_in   = (const float*)d_in[0];
    const float* td_energy = (const float*)d_in[1];
    const float* td_hist   = (const float*)d_in[2];

    float* out        = (float*)d_out;
    float* out_energy = out + N_DATA;
    float* out_hist   = out_energy + C;

    init_energy<<<1, C>>>(td_energy, out_energy);
    fused_bulk<<<(B / 2) * C, 256>>>((const float4*)data_in, (float4*)out,
                                     td_hist, out_energy, out_hist);
}